// round 2
// baseline (speedup 1.0000x reference)
#include <cuda_runtime.h>
#include <cuda_bf16.h>
#include <cstdint>

#define N_NODES 4096
#define IN_F 128
#define OUT_F 128

// Scratch for the per-node transformed features (out1 = rel @ (W @ x)), [N, OUT_F]
__device__ float g_out1[N_NODES * OUT_F];

// ---------------------------------------------------------------------------
// Kernel 1: per-node  support = x_n @ W_n  then  out1_n = R_n @ support
// One block per node, 128 threads.  HBM-streaming bound (512 MB total).
// ---------------------------------------------------------------------------
__global__ __launch_bounds__(128) void node_transform_kernel(
    const float* __restrict__ input,   // [N, IN_F]
    const float* __restrict__ rel,     // [N, OUT_F, OUT_F]
    const float* __restrict__ W)       // [N, IN_F, OUT_F]
{
    const int n = blockIdx.x;
    const int t = threadIdx.x;               // 0..127

    __shared__ float in_row[IN_F];
    __shared__ float s_vec[OUT_F];

    in_row[t] = input[(size_t)n * IN_F + t];
    __syncthreads();

    // ---- phase 1: support[k] = sum_j x[j] * W[j,k]; thread t owns k = t.
    // Reads of W are coalesced across threads (consecutive k).
    const float* __restrict__ Wn = W + (size_t)n * IN_F * OUT_F;
    float acc = 0.0f;
#pragma unroll 8
    for (int j = 0; j < IN_F; ++j) {
        acc += in_row[j] * Wn[(size_t)j * OUT_F + t];
    }
    s_vec[t] = acc;
    __syncthreads();

    // ---- phase 2: out1[j] = sum_k R[j,k] * s[k]
    // Warp w handles 32 j-rows; lanes split k (float4 each) -> coalesced rel reads.
    const int w = t >> 5;
    const int l = t & 31;
    const float4 s4 = *reinterpret_cast<const float4*>(&s_vec[4 * l]);
    const float* __restrict__ Rn = rel + (size_t)n * OUT_F * OUT_F;

#pragma unroll 4
    for (int jj = 0; jj < 32; ++jj) {
        const int j = w * 32 + jj;
        const float4 r4 = *reinterpret_cast<const float4*>(&Rn[(size_t)j * OUT_F + 4 * l]);
        float p = r4.x * s4.x + r4.y * s4.y + r4.z * s4.z + r4.w * s4.w;
#pragma unroll
        for (int off = 16; off > 0; off >>= 1)
            p += __shfl_xor_sync(0xffffffffu, p, off);
        if (l == jj)  // every lane eventually writes one value; no divergence penalty
            g_out1[(size_t)n * OUT_F + j] = p;
    }
}

// ---------------------------------------------------------------------------
// Kernel 2: C = adj @ out1 + bias   (M=4096, N=128, K=4096, fp32)
// BM=32, BN=128 (full N), BK=32, 256 threads, 4x4 microtile, double-buffered.
// Grid = 128 blocks ~ one wave over 148 SMs.
// ---------------------------------------------------------------------------
#define BM 32
#define BN 128
#define BK 32
#define KDIM 4096
#define NT (KDIM / BK)   // 128 k-tiles

__global__ __launch_bounds__(256) void agg_gemm_kernel(
    const float* __restrict__ A,     // adj [4096, 4096]
    const float* __restrict__ bias,  // [128]
    float* __restrict__ C)           // [4096, 128]
{
    __shared__ float As[2][BK][BM + 4];  // transposed A tile, padded for alignment
    __shared__ float Bs[2][BK][BN];

    const float* __restrict__ B = g_out1;

    const int t  = threadIdx.x;
    const int m0 = blockIdx.x * BM;

    // compute mapping: warp w = t/32 owns rows 4w..4w+3, lane owns cols 4*tn..4*tn+3
    const int tm = t >> 5;   // 0..7
    const int tn = t & 31;   // 0..31

    // load mapping for A tile (BMxBK = 1024 floats, 4 per thread, vectorized)
    const int am  = t >> 3;        // 0..31  (row within tile)
    const int ak4 = (t & 7) * 4;   // 0,4,...,28 (k within tile)
    // load mapping for B tile (BKxBN = 4096 floats, 16 per thread)
    const int brow = t >> 5;       // 0..7, stride 8 over 4 iters
    const int bcol = tn * 4;

    float acc[4][4];
#pragma unroll
    for (int i = 0; i < 4; ++i)
#pragma unroll
        for (int j = 0; j < 4; ++j) acc[i][j] = 0.0f;

    // ---- prologue: load tile 0 into buffer 0
    {
        const float4 a4 = *reinterpret_cast<const float4*>(
            &A[(size_t)(m0 + am) * KDIM + ak4]);
        As[0][ak4 + 0][am] = a4.x;
        As[0][ak4 + 1][am] = a4.y;
        As[0][ak4 + 2][am] = a4.z;
        As[0][ak4 + 3][am] = a4.w;
#pragma unroll
        for (int r = 0; r < 4; ++r) {
            const int bk = brow + 8 * r;
            *reinterpret_cast<float4*>(&Bs[0][bk][bcol]) =
                *reinterpret_cast<const float4*>(&B[(size_t)bk * BN + bcol]);
        }
    }
    __syncthreads();

    int buf = 0;
    for (int kt = 0; kt < NT; ++kt) {
        float4 aReg;
        float4 bReg[4];
        const bool have_next = (kt + 1) < NT;

        // prefetch next tile from global into registers (overlaps compute)
        if (have_next) {
            const int kbase = (kt + 1) * BK;
            aReg = *reinterpret_cast<const float4*>(
                &A[(size_t)(m0 + am) * KDIM + kbase + ak4]);
#pragma unroll
            for (int r = 0; r < 4; ++r) {
                const int bk = brow + 8 * r;
                bReg[r] = *reinterpret_cast<const float4*>(
                    &B[(size_t)(kbase + bk) * BN + bcol]);
            }
        }

        // compute on current buffer
#pragma unroll
        for (int kk = 0; kk < BK; ++kk) {
            const float4 a4 = *reinterpret_cast<const float4*>(&As[buf][kk][4 * tm]);
            const float4 b4 = *reinterpret_cast<const float4*>(&Bs[buf][kk][4 * tn]);
            const float a[4] = {a4.x, a4.y, a4.z, a4.w};
            const float b[4] = {b4.x, b4.y, b4.z, b4.w};
#pragma unroll
            for (int i = 0; i < 4; ++i)
#pragma unroll
                for (int j = 0; j < 4; ++j)
                    acc[i][j] += a[i] * b[j];
        }

        if (have_next) {
            const int nb = buf ^ 1;
            As[nb][ak4 + 0][am] = aReg.x;
            As[nb][ak4 + 1][am] = aReg.y;
            As[nb][ak4 + 2][am] = aReg.z;
            As[nb][ak4 + 3][am] = aReg.w;
#pragma unroll
            for (int r = 0; r < 4; ++r) {
                const int bk = brow + 8 * r;
                *reinterpret_cast<float4*>(&Bs[nb][bk][bcol]) = bReg[r];
            }
            __syncthreads();
            buf = nb;
        }
    }

    // ---- epilogue: add bias, vectorized store
    const float4 bia = *reinterpret_cast<const float4*>(&bias[4 * tn]);
#pragma unroll
    for (int i = 0; i < 4; ++i) {
        const int m = m0 + 4 * tm + i;
        float4 o;
        o.x = acc[i][0] + bia.x;
        o.y = acc[i][1] + bia.y;
        o.z = acc[i][2] + bia.z;
        o.w = acc[i][3] + bia.w;
        *reinterpret_cast<float4*>(&C[(size_t)m * BN + 4 * tn]) = o;
    }
}

extern "C" void kernel_launch(void* const* d_in, const int* in_sizes, int n_in,
                              void* d_out, int out_size)
{
    const float* input = (const float*)d_in[0];  // [4096, 128]
    const float* adj   = (const float*)d_in[1];  // [4096, 4096]
    const float* rel   = (const float*)d_in[2];  // [4096, 128, 128]
    const float* W     = (const float*)d_in[3];  // [4096, 128, 128]
    const float* bias  = (const float*)d_in[4];  // [128]
    float* out = (float*)d_out;                  // [4096, 128]

    node_transform_kernel<<<N_NODES, 128>>>(input, rel, W);
    agg_gemm_kernel<<<KDIM / BM, 256>>>(adj, bias, out);
}

// round 4
// speedup vs baseline: 1.6296x; 1.6296x over previous
#include <cuda_runtime.h>
#include <cuda_bf16.h>
#include <cstdint>

#define N_NODES 4096
#define FEA 128
#define KD 4096
#define SPLITS 4
#define KSPL (KD / SPLITS)       // 1024
#define BK 64                    // k per tile (128B bf16 rows)
#define TILES (KSPL / BK)        // 16

// ---------------- device scratch (no allocations allowed) -------------------
__device__ __nv_bfloat16 g_b_hi[(size_t)FEA * N_NODES];  // out1^T hi  [f][node]
__device__ __nv_bfloat16 g_b_lo[(size_t)FEA * N_NODES];  // out1^T lo
__device__ float g_part[SPLITS][(size_t)N_NODES * FEA];  // split-K partials

// ---------------- helpers ----------------------------------------------------
__device__ __forceinline__ uint32_t smem_u32(const void* p) {
    uint32_t a;
    asm("{ .reg .u64 t; cvta.to.shared.u64 t, %1; cvt.u32.u64 %0, t; }"
        : "=r"(a) : "l"(p));
    return a;
}
__device__ __forceinline__ void ldsm4(uint32_t* r, uint32_t addr) {
    asm volatile("ldmatrix.sync.aligned.m8n8.x4.shared.b16 {%0,%1,%2,%3}, [%4];"
                 : "=r"(r[0]), "=r"(r[1]), "=r"(r[2]), "=r"(r[3]) : "r"(addr));
}
__device__ __forceinline__ void mma16816(float* c, const uint32_t* a,
                                         const uint32_t* b) {
    asm volatile(
        "mma.sync.aligned.m16n8k16.row.col.f32.bf16.bf16.f32 "
        "{%0,%1,%2,%3}, {%4,%5,%6,%7}, {%8,%9}, {%0,%1,%2,%3};"
        : "+f"(c[0]), "+f"(c[1]), "+f"(c[2]), "+f"(c[3])
        : "r"(a[0]), "r"(a[1]), "r"(a[2]), "r"(a[3]), "r"(b[0]), "r"(b[1]));
}
__device__ __forceinline__ void cp16(uint32_t dst, const void* src) {
    asm volatile("cp.async.cg.shared.global [%0], [%1], 16;"
                 :: "r"(dst), "l"(src) : "memory");
}
__device__ __forceinline__ void cp_commit() {
    asm volatile("cp.async.commit_group;" ::: "memory");
}
__device__ __forceinline__ void cp_wait0() {
    asm volatile("cp.async.wait_group 0;" ::: "memory");
}

#define SWZ(o) ((uint32_t)(o) ^ ((((uint32_t)(o)) >> 3) & 0x70u))

__device__ __forceinline__ uint32_t bf2_pack(__nv_bfloat16 a, __nv_bfloat16 b) {
    __nv_bfloat162 v; v.x = a; v.y = b;
    return *reinterpret_cast<uint32_t*>(&v);
}

// ---------------------------------------------------------------------------
// Kernel 1: per-node  support = x_n @ W_n, then out1_n = R_n @ support.
// Emits out1 TRANSPOSED as bf16 (hi, lo): B[f][node], K-major for the GEMM.
// HBM streaming bound (512 MB).
// ---------------------------------------------------------------------------
__global__ __launch_bounds__(128) void node_transform_kernel(
    const float* __restrict__ input,   // [N, 128]
    const float* __restrict__ rel,     // [N, 128, 128]
    const float* __restrict__ W)       // [N, 128, 128]
{
    const int n = blockIdx.x;
    const int t = threadIdx.x;

    __shared__ float in_row[FEA];
    __shared__ float s_vec[FEA];

    in_row[t] = input[(size_t)n * FEA + t];
    __syncthreads();

    const float* __restrict__ Wn = W + (size_t)n * FEA * FEA;
    float acc = 0.0f;
#pragma unroll 8
    for (int j = 0; j < FEA; ++j)
        acc += in_row[j] * Wn[(size_t)j * FEA + t];
    s_vec[t] = acc;
    __syncthreads();

    const int w = t >> 5;
    const int l = t & 31;
    const float4 s4 = *reinterpret_cast<const float4*>(&s_vec[4 * l]);
    const float* __restrict__ Rn = rel + (size_t)n * FEA * FEA;

#pragma unroll 4
    for (int jj = 0; jj < 32; ++jj) {
        const int j = w * 32 + jj;
        const float4 r4 = *reinterpret_cast<const float4*>(&Rn[(size_t)j * FEA + 4 * l]);
        float p = r4.x * s4.x + r4.y * s4.y + r4.z * s4.z + r4.w * s4.w;
#pragma unroll
        for (int off = 16; off > 0; off >>= 1)
            p += __shfl_xor_sync(0xffffffffu, p, off);
        if (l == jj) {
            __nv_bfloat16 h = __float2bfloat16(p);
            float r = p - __bfloat162float(h);
            g_b_hi[(size_t)j * N_NODES + n] = h;
            g_b_lo[(size_t)j * N_NODES + n] = __float2bfloat16(r);
        }
    }
}

// ---------------------------------------------------------------------------
// Kernel 2: split-K HMMA GEMM.  partial[s] = adj[:, sK:(s+1)K] @ out1[sK:..]
// CTA tile 128x128, BK=64, double-buffered smem, 8 warps (4M x 2N).
// A split into bf16 hi/lo on the fly; 3 mma products per frag (hh, hl, lh).
// ---------------------------------------------------------------------------
#define TILE_B 16384                        // one operand tile: 128 x 64 bf16
#define BUF_B (4 * TILE_B)                  // A_hi, A_lo, B_hi, B_lo
#define SMEM_REQ (2 * BUF_B + 1024)

__global__ __launch_bounds__(256, 1) void hmma_gemm_kernel(const float* __restrict__ A)
{
    extern __shared__ char dsm[];
    const uint32_t raw  = smem_u32(dsm);
    const uint32_t base = (raw + 1023u) & ~1023u;
    char* smb = dsm + (base - raw);

    const int t   = threadIdx.x;
    const int wid = t >> 5;
    const int l   = t & 31;
    const int m0  = blockIdx.x * 128;
    const int kb0 = blockIdx.y * KSPL;

    const int warpM = wid & 3;   // 0..3 -> 32 rows each
    const int warpN = wid >> 2;  // 0..1 -> 64 cols each

    // ---- per-lane ldmatrix address components (byte offsets within tile) ----
    // A (x4 over m16 x k16): rows = mbase + (l&15), k-half = (l>>4)*16 bytes
    uint32_t aRowOff[2], aXor[2];
#pragma unroll
    for (int mf = 0; mf < 2; ++mf) {
        const int r = warpM * 32 + mf * 16 + (l & 15);
        aRowOff[mf] = r * 128;
        aXor[mf]    = (r & 7) * 16;
    }
    const uint32_t aK = (l >> 4) * 16;
    // B (x4 over 2 n-frags x k16): rows = nbase + (l>>4)*8 + (l&7),
    //                              k-half = ((l>>3)&1)*16 bytes
    uint32_t bRowOff[4], bXor[4];
#pragma unroll
    for (int q = 0; q < 4; ++q) {
        const int r = warpN * 64 + q * 16 + ((l >> 4) << 3) + (l & 7);
        bRowOff[q] = r * 128;
        bXor[q]    = (r & 7) * 16;
    }
    const uint32_t bK = ((l >> 3) & 1) * 16;

    // ---- staging maps ----
    const int aRow = t >> 1;                 // A: 128 rows, 2 threads/row
    const int aC4  = (t & 1) * 8;            // float4 idx 0..15, 8 per thread
    const int bRow = t >> 1;                 // B: 128 rows, 2 threads/row
    const int bC   = (t & 1) * 4;            // 16B chunk idx 0..7, 4 per thread

    float c[2][8][4];
#pragma unroll
    for (int i = 0; i < 2; ++i)
#pragma unroll
        for (int j = 0; j < 8; ++j)
#pragma unroll
            for (int k = 0; k < 4; ++k) c[i][j][k] = 0.0f;

    float4 aPre[8];

    // ================== prologue: stage tile 0 into buffer 0 =================
    {
        const uint32_t bH = 2 * TILE_B, bL = 3 * TILE_B;
#pragma unroll
        for (int r = 0; r < 4; ++r) {
            const uint32_t dof = SWZ(bRow * 128 + (bC + r) * 16);
            const size_t   src = (size_t)bRow * KD + kb0 + (bC + r) * 8;
            cp16(base + bH + dof, &g_b_hi[src]);
            cp16(base + bL + dof, &g_b_lo[src]);
        }
        cp_commit();
#pragma unroll
        for (int r = 0; r < 8; ++r)
            aPre[r] = *reinterpret_cast<const float4*>(
                &A[(size_t)(m0 + aRow) * KD + kb0 + ((aC4 + r) << 2)]);
#pragma unroll
        for (int r = 0; r < 8; ++r) {
            const float4 v = aPre[r];
            const __nv_bfloat16 h0 = __float2bfloat16(v.x);
            const __nv_bfloat16 h1 = __float2bfloat16(v.y);
            const __nv_bfloat16 h2 = __float2bfloat16(v.z);
            const __nv_bfloat16 h3 = __float2bfloat16(v.w);
            uint2 hv, lv;
            hv.x = bf2_pack(h0, h1); hv.y = bf2_pack(h2, h3);
            lv.x = bf2_pack(__float2bfloat16(v.x - __bfloat162float(h0)),
                            __float2bfloat16(v.y - __bfloat162float(h1)));
            lv.y = bf2_pack(__float2bfloat16(v.z - __bfloat162float(h2)),
                            __float2bfloat16(v.w - __bfloat162float(h3)));
            const uint32_t off = SWZ(aRow * 128 + (aC4 + r) * 8);
            *reinterpret_cast<uint2*>(smb + off) = hv;
            *reinterpret_cast<uint2*>(smb + TILE_B + off) = lv;
        }
        cp_wait0();
        __syncthreads();
    }

    // ================== main loop =============================================
    for (int kt = 0; kt < TILES; ++kt) {
        const uint32_t cur = (kt & 1) * BUF_B;
        const uint32_t nxt = cur ^ BUF_B;
        const bool have_next = (kt + 1) < TILES;

        if (have_next) {
            const int kb = kb0 + (kt + 1) * BK;
#pragma unroll
            for (int r = 0; r < 4; ++r) {
                const uint32_t dof = SWZ(bRow * 128 + (bC + r) * 16);
                const size_t   src = (size_t)bRow * KD + kb + (bC + r) * 8;
                cp16(base + nxt + 2 * TILE_B + dof, &g_b_hi[src]);
                cp16(base + nxt + 3 * TILE_B + dof, &g_b_lo[src]);
            }
            cp_commit();
#pragma unroll
            for (int r = 0; r < 8; ++r)
                aPre[r] = *reinterpret_cast<const float4*>(
                    &A[(size_t)(m0 + aRow) * KD + kb + ((aC4 + r) << 2)]);
        }

        // ---- compute on current buffer: 4 k-steps of 16 ----
        const uint32_t aHb = base + cur;
        const uint32_t aLb = aHb + TILE_B;
        const uint32_t bHb = aHb + 2 * TILE_B;
        const uint32_t bLb = aHb + 3 * TILE_B;
#pragma unroll
        for (int st = 0; st < 4; ++st) {
            const uint32_t k2 = st * 32;
            uint32_t ah[2][4], al[2][4];
#pragma unroll
            for (int mf = 0; mf < 2; ++mf) {
                const uint32_t off = aRowOff[mf] + ((aK + k2) ^ aXor[mf]);
                ldsm4(ah[mf], aHb + off);
                ldsm4(al[mf], aLb + off);
            }
            uint32_t bh[4][4], bl[4][4];
#pragma unroll
            for (int q = 0; q < 4; ++q) {
                const uint32_t off = bRowOff[q] + ((bK + k2) ^ bXor[q]);
                ldsm4(bh[q], bHb + off);
                ldsm4(bl[q], bLb + off);
            }
#pragma unroll
            for (int mf = 0; mf < 2; ++mf)
#pragma unroll
                for (int q = 0; q < 4; ++q)
#pragma unroll
                    for (int h = 0; h < 2; ++h) {
                        float* cc = c[mf][2 * q + h];
                        mma16816(cc, ah[mf], &bh[q][2 * h]);
                        mma16816(cc, ah[mf], &bl[q][2 * h]);
                        mma16816(cc, al[mf], &bh[q][2 * h]);
                    }
        }

        if (have_next) {
#pragma unroll
            for (int r = 0; r < 8; ++r) {
                const float4 v = aPre[r];
                const __nv_bfloat16 h0 = __float2bfloat16(v.x);
                const __nv_bfloat16 h1 = __float2bfloat16(v.y);
                const __nv_bfloat16 h2 = __float2bfloat16(v.z);
                const __nv_bfloat16 h3 = __float2bfloat16(v.w);
                uint2 hv, lv;
                hv.x = bf2_pack(h0, h1); hv.y = bf2_pack(h2, h3);
                lv.x = bf2_pack(__float2bfloat16(v.x - __bfloat162float(h0)),
                                __float2bfloat16(v.y - __bfloat162float(h1)));
                lv.y = bf2_pack(__float2bfloat16(v.z - __bfloat162float(h2)),
                                __float2bfloat16(v.w - __bfloat162float(h3)));
                const uint32_t off = SWZ(aRow * 128 + (aC4 + r) * 8);
                *reinterpret_cast<uint2*>(smb + nxt + off) = hv;
                *reinterpret_cast<uint2*>(smb + nxt + TILE_B + off) = lv;
            }
            cp_wait0();
            __syncthreads();
        }
    }

    // ---- epilogue: write fp32 partials ----
    float* __restrict__ part = g_part[blockIdx.y];
    const int cRow = (l >> 2);
    const int cCol = (l & 3) * 2;
#pragma unroll
    for (int mf = 0; mf < 2; ++mf) {
        const int rbase = m0 + warpM * 32 + mf * 16 + cRow;
#pragma unroll
        for (int nf = 0; nf < 8; ++nf) {
            const int col = warpN * 64 + nf * 8 + cCol;
            float2 v0; v0.x = c[mf][nf][0]; v0.y = c[mf][nf][1];
            float2 v1; v1.x = c[mf][nf][2]; v1.y = c[mf][nf][3];
            *reinterpret_cast<float2*>(&part[(size_t)rbase * FEA + col])       = v0;
            *reinterpret_cast<float2*>(&part[(size_t)(rbase + 8) * FEA + col]) = v1;
        }
    }
}

// ---------------------------------------------------------------------------
// Kernel 3: sum 4 split-K partials + bias.
// ---------------------------------------------------------------------------
__global__ __launch_bounds__(256) void reduce_kernel(
    const float* __restrict__ bias, float* __restrict__ out)
{
    const int i = blockIdx.x * 256 + threadIdx.x;  // float4 index
    const float4 a = reinterpret_cast<const float4*>(g_part[0])[i];
    const float4 b = reinterpret_cast<const float4*>(g_part[1])[i];
    const float4 c = reinterpret_cast<const float4*>(g_part[2])[i];
    const float4 d = reinterpret_cast<const float4*>(g_part[3])[i];
    const float4 bi = *reinterpret_cast<const float4*>(&bias[(i & 31) << 2]);
    float4 o;
    o.x = a.x + b.x + c.x + d.x + bi.x;
    o.y = a.y + b.y + c.y + d.y + bi.y;
    o.z = a.z + b.z + c.z + d.z + bi.z;
    o.w = a.w + b.w + c.w + d.w + bi.w;
    reinterpret_cast<float4*>(out)[i] = o;
}

extern "C" void kernel_launch(void* const* d_in, const int* in_sizes, int n_in,
                              void* d_out, int out_size)
{
    const float* input = (const float*)d_in[0];  // [4096, 128]
    const float* adj   = (const float*)d_in[1];  // [4096, 4096]
    const float* rel   = (const float*)d_in[2];  // [4096, 128, 128]
    const float* W     = (const float*)d_in[3];  // [4096, 128, 128]
    const float* bias  = (const float*)d_in[4];  // [128]
    float* out = (float*)d_out;                  // [4096, 128]

    cudaFuncSetAttribute(hmma_gemm_kernel,
                         cudaFuncAttributeMaxDynamicSharedMemorySize, SMEM_REQ);

    node_transform_kernel<<<N_NODES, 128>>>(input, rel, W);
    hmma_gemm_kernel<<<dim3(32, SPLITS), 256, SMEM_REQ>>>(adj);
    reduce_kernel<<<(N_NODES * FEA / 4) / 256, 256>>>(bias, out);
}

// round 5
// speedup vs baseline: 1.6475x; 1.0110x over previous
#include <cuda_runtime.h>
#include <cuda_bf16.h>
#include <cstdint>

#define N_NODES 4096
#define FEA 128
#define KD 4096
#define SPLITS 4
#define KSPL (KD / SPLITS)       // 1024
#define BK 64                    // k per tile (128B bf16 rows)
#define TILES (KSPL / BK)        // 16

// ---------------- device scratch (no allocations allowed) -------------------
__device__ __nv_bfloat16 g_b_hi[(size_t)FEA * N_NODES];  // out1^T hi  [f][node]
__device__ __nv_bfloat16 g_b_lo[(size_t)FEA * N_NODES];  // out1^T lo
__device__ float g_part[SPLITS][(size_t)N_NODES * FEA];  // split-K partials

// ---------------- helpers ----------------------------------------------------
__device__ __forceinline__ uint32_t smem_u32(const void* p) {
    uint32_t a;
    asm("{ .reg .u64 t; cvta.to.shared.u64 t, %1; cvt.u32.u64 %0, t; }"
        : "=r"(a) : "l"(p));
    return a;
}
__device__ __forceinline__ void ldsm4(uint32_t* r, uint32_t addr) {
    asm volatile("ldmatrix.sync.aligned.m8n8.x4.shared.b16 {%0,%1,%2,%3}, [%4];"
                 : "=r"(r[0]), "=r"(r[1]), "=r"(r[2]), "=r"(r[3]) : "r"(addr));
}
__device__ __forceinline__ void mma16816(float* c, const uint32_t* a,
                                         const uint32_t* b) {
    asm volatile(
        "mma.sync.aligned.m16n8k16.row.col.f32.bf16.bf16.f32 "
        "{%0,%1,%2,%3}, {%4,%5,%6,%7}, {%8,%9}, {%0,%1,%2,%3};"
        : "+f"(c[0]), "+f"(c[1]), "+f"(c[2]), "+f"(c[3])
        : "r"(a[0]), "r"(a[1]), "r"(a[2]), "r"(a[3]), "r"(b[0]), "r"(b[1]));
}
__device__ __forceinline__ void cp16(uint32_t dst, const void* src) {
    asm volatile("cp.async.cg.shared.global [%0], [%1], 16;"
                 :: "r"(dst), "l"(src) : "memory");
}
__device__ __forceinline__ void cp_commit() {
    asm volatile("cp.async.commit_group;" ::: "memory");
}
__device__ __forceinline__ void cp_wait0() {
    asm volatile("cp.async.wait_group 0;" ::: "memory");
}

#define SWZ(o) ((uint32_t)(o) ^ ((((uint32_t)(o)) >> 3) & 0x70u))

__device__ __forceinline__ uint32_t bf2_pack(__nv_bfloat16 a, __nv_bfloat16 b) {
    __nv_bfloat162 v; v.x = a; v.y = b;
    return *reinterpret_cast<uint32_t*>(&v);
}

// ---------------------------------------------------------------------------
// Kernel 1: per-node  support = x_n @ W_n, then out1_n = R_n @ support.
// Phase 1 fully vectorized (LDG.128 on the W stream).
// Emits out1 TRANSPOSED as bf16 (hi, lo): B[f][node], K-major for the GEMM.
// ---------------------------------------------------------------------------
__global__ __launch_bounds__(128) void node_transform_kernel(
    const float* __restrict__ input,   // [N, 128]
    const float* __restrict__ rel,     // [N, 128, 128]
    const float* __restrict__ W)       // [N, 128, 128]
{
    const int n = blockIdx.x;
    const int t = threadIdx.x;

    __shared__ float in_row[FEA];
    __shared__ float s_vec[FEA];
    __shared__ float partf[4][FEA];

    in_row[t] = input[(size_t)n * FEA + t];
    __syncthreads();

    // ---- phase 1: support = x @ W, vectorized.
    // Warp g (=t>>5) covers j in [32g, 32g+32); lane q (=t&31) owns k-quad 4q.
    {
        const int q = t & 31, g = t >> 5;
        const float* __restrict__ Wn = W + (size_t)n * FEA * FEA;
        float4 acc4 = make_float4(0.f, 0.f, 0.f, 0.f);
#pragma unroll 8
        for (int jj = 0; jj < 32; ++jj) {
            const int j = g * 32 + jj;
            const float4 w4 = *reinterpret_cast<const float4*>(
                &Wn[(size_t)j * FEA + 4 * q]);
            const float x = in_row[j];
            acc4.x += x * w4.x; acc4.y += x * w4.y;
            acc4.z += x * w4.z; acc4.w += x * w4.w;
        }
        *reinterpret_cast<float4*>(&partf[g][4 * q]) = acc4;
        __syncthreads();
        s_vec[t] = partf[0][t] + partf[1][t] + partf[2][t] + partf[3][t];
        __syncthreads();
    }

    // ---- phase 2: out1[j] = sum_k R[j,k] * s[k]  (coalesced float4 + shuffle)
    const int w = t >> 5;
    const int l = t & 31;
    const float4 s4 = *reinterpret_cast<const float4*>(&s_vec[4 * l]);
    const float* __restrict__ Rn = rel + (size_t)n * FEA * FEA;

#pragma unroll 4
    for (int jj = 0; jj < 32; ++jj) {
        const int j = w * 32 + jj;
        const float4 r4 = *reinterpret_cast<const float4*>(&Rn[(size_t)j * FEA + 4 * l]);
        float p = r4.x * s4.x + r4.y * s4.y + r4.z * s4.z + r4.w * s4.w;
#pragma unroll
        for (int off = 16; off > 0; off >>= 1)
            p += __shfl_xor_sync(0xffffffffu, p, off);
        if (l == jj) {
            __nv_bfloat16 h = __float2bfloat16(p);
            float r = p - __bfloat162float(h);
            g_b_hi[(size_t)j * N_NODES + n] = h;
            g_b_lo[(size_t)j * N_NODES + n] = __float2bfloat16(r);
        }
    }
}

// ---------------------------------------------------------------------------
// Kernel 2: split-K HMMA GEMM.  partial[s] = adj[:, sK:(s+1)K] @ out1[sK:..]
// CTA tile 128x128, BK=64, double-buffered smem, 8 warps (4M x 2N).
// A split into bf16 hi/lo on the fly; conversion overlapped with MMA compute.
// ---------------------------------------------------------------------------
#define TILE_B 16384                        // one operand tile: 128 x 64 bf16
#define BUF_B (4 * TILE_B)                  // A_hi, A_lo, B_hi, B_lo
#define SMEM_REQ (2 * BUF_B + 1024)

__global__ __launch_bounds__(256, 1) void hmma_gemm_kernel(const float* __restrict__ A)
{
    extern __shared__ char dsm[];
    const uint32_t raw  = smem_u32(dsm);
    const uint32_t base = (raw + 1023u) & ~1023u;
    char* smb = dsm + (base - raw);

    const int t   = threadIdx.x;
    const int wid = t >> 5;
    const int l   = t & 31;
    const int m0  = blockIdx.x * 128;
    const int kb0 = blockIdx.y * KSPL;

    const int warpM = wid & 3;   // 0..3 -> 32 rows each
    const int warpN = wid >> 2;  // 0..1 -> 64 cols each

    // ---- per-lane ldmatrix address components (byte offsets within tile) ----
    uint32_t aRowOff[2], aXor[2];
#pragma unroll
    for (int mf = 0; mf < 2; ++mf) {
        const int r = warpM * 32 + mf * 16 + (l & 15);
        aRowOff[mf] = r * 128;
        aXor[mf]    = (r & 7) * 16;
    }
    const uint32_t aK = (l >> 4) * 16;
    uint32_t bRowOff[4], bXor[4];
#pragma unroll
    for (int q = 0; q < 4; ++q) {
        const int r = warpN * 64 + q * 16 + ((l >> 4) << 3) + (l & 7);
        bRowOff[q] = r * 128;
        bXor[q]    = (r & 7) * 16;
    }
    const uint32_t bK = ((l >> 3) & 1) * 16;

    // ---- staging maps ----
    const int aRow = t >> 1;                 // A: 128 rows, 2 threads/row
    const int aC4  = (t & 1) * 8;            // float4 idx, 8 per thread
    const int bRow = t >> 1;                 // B: 128 rows, 2 threads/row
    const int bC   = (t & 1) * 4;            // 16B chunk idx, 4 per thread

    float c[2][8][4];
#pragma unroll
    for (int i = 0; i < 2; ++i)
#pragma unroll
        for (int j = 0; j < 8; ++j)
#pragma unroll
            for (int k = 0; k < 4; ++k) c[i][j][k] = 0.0f;

    float4 aPre[8];

    // convert aPre -> bf16 hi/lo tiles at smem byte offset `dst`
    auto convert_store = [&](uint32_t dst) {
#pragma unroll
        for (int r = 0; r < 8; ++r) {
            const float4 v = aPre[r];
            const __nv_bfloat16 h0 = __float2bfloat16(v.x);
            const __nv_bfloat16 h1 = __float2bfloat16(v.y);
            const __nv_bfloat16 h2 = __float2bfloat16(v.z);
            const __nv_bfloat16 h3 = __float2bfloat16(v.w);
            uint2 hv, lv;
            hv.x = bf2_pack(h0, h1); hv.y = bf2_pack(h2, h3);
            lv.x = bf2_pack(__float2bfloat16(v.x - __bfloat162float(h0)),
                            __float2bfloat16(v.y - __bfloat162float(h1)));
            lv.y = bf2_pack(__float2bfloat16(v.z - __bfloat162float(h2)),
                            __float2bfloat16(v.w - __bfloat162float(h3)));
            const uint32_t off = SWZ(aRow * 128 + (aC4 + r) * 8);
            *reinterpret_cast<uint2*>(smb + dst + off) = hv;
            *reinterpret_cast<uint2*>(smb + dst + TILE_B + off) = lv;
        }
    };

    // one k16 compute step on buffer at byte offset `cur`
    auto compute_step = [&](uint32_t cur, int st) {
        const uint32_t aHb = base + cur;
        const uint32_t aLb = aHb + TILE_B;
        const uint32_t bHb = aHb + 2 * TILE_B;
        const uint32_t bLb = aHb + 3 * TILE_B;
        const uint32_t k2 = st * 32;
        uint32_t ah[2][4], al[2][4];
#pragma unroll
        for (int mf = 0; mf < 2; ++mf) {
            const uint32_t off = aRowOff[mf] + ((aK + k2) ^ aXor[mf]);
            ldsm4(ah[mf], aHb + off);
            ldsm4(al[mf], aLb + off);
        }
        uint32_t bh[4][4], bl[4][4];
#pragma unroll
        for (int q = 0; q < 4; ++q) {
            const uint32_t off = bRowOff[q] + ((bK + k2) ^ bXor[q]);
            ldsm4(bh[q], bHb + off);
            ldsm4(bl[q], bLb + off);
        }
#pragma unroll
        for (int mf = 0; mf < 2; ++mf)
#pragma unroll
            for (int q = 0; q < 4; ++q)
#pragma unroll
                for (int h = 0; h < 2; ++h) {
                    float* cc = c[mf][2 * q + h];
                    mma16816(cc, ah[mf], &bh[q][2 * h]);
                    mma16816(cc, ah[mf], &bl[q][2 * h]);
                    mma16816(cc, al[mf], &bh[q][2 * h]);
                }
    };

    // ================== prologue: stage tile 0 into buffer 0 =================
    {
#pragma unroll
        for (int r = 0; r < 4; ++r) {
            const uint32_t dof = SWZ(bRow * 128 + (bC + r) * 16);
            const size_t   src = (size_t)bRow * KD + kb0 + (bC + r) * 8;
            cp16(base + 2 * TILE_B + dof, &g_b_hi[src]);
            cp16(base + 3 * TILE_B + dof, &g_b_lo[src]);
        }
        cp_commit();
#pragma unroll
        for (int r = 0; r < 8; ++r)
            aPre[r] = *reinterpret_cast<const float4*>(
                &A[(size_t)(m0 + aRow) * KD + kb0 + ((aC4 + r) << 2)]);
        convert_store(0);
        cp_wait0();
        __syncthreads();
    }

    // ================== main loop =============================================
    for (int kt = 0; kt < TILES; ++kt) {
        const uint32_t cur = (kt & 1) * BUF_B;
        const uint32_t nxt = cur ^ BUF_B;
        const bool have_next = (kt + 1) < TILES;

        if (have_next) {
            const int kb = kb0 + (kt + 1) * BK;
#pragma unroll
            for (int r = 0; r < 4; ++r) {
                const uint32_t dof = SWZ(bRow * 128 + (bC + r) * 16);
                const size_t   src = (size_t)bRow * KD + kb + (bC + r) * 8;
                cp16(base + nxt + 2 * TILE_B + dof, &g_b_hi[src]);
                cp16(base + nxt + 3 * TILE_B + dof, &g_b_lo[src]);
            }
            cp_commit();
#pragma unroll
            for (int r = 0; r < 8; ++r)
                aPre[r] = *reinterpret_cast<const float4*>(
                    &A[(size_t)(m0 + aRow) * KD + kb + ((aC4 + r) << 2)]);
        }

        // compute first half (covers A LDG latency)
        compute_step(cur, 0);
        compute_step(cur, 1);

        // conversion overlapped between the two compute halves
        if (have_next) convert_store(nxt);

        compute_step(cur, 2);
        compute_step(cur, 3);

        if (have_next) {
            cp_wait0();
            __syncthreads();
        }
    }

    // ---- epilogue: write fp32 partials ----
    float* __restrict__ part = g_part[blockIdx.y];
    const int cRow = (l >> 2);
    const int cCol = (l & 3) * 2;
#pragma unroll
    for (int mf = 0; mf < 2; ++mf) {
        const int rbase = m0 + warpM * 32 + mf * 16 + cRow;
#pragma unroll
        for (int nf = 0; nf < 8; ++nf) {
            const int col = warpN * 64 + nf * 8 + cCol;
            float2 v0; v0.x = c[mf][nf][0]; v0.y = c[mf][nf][1];
            float2 v1; v1.x = c[mf][nf][2]; v1.y = c[mf][nf][3];
            *reinterpret_cast<float2*>(&part[(size_t)rbase * FEA + col])       = v0;
            *reinterpret_cast<float2*>(&part[(size_t)(rbase + 8) * FEA + col]) = v1;
        }
    }
}

// ---------------------------------------------------------------------------
// Kernel 3: sum 4 split-K partials + bias.
// ---------------------------------------------------------------------------
__global__ __launch_bounds__(256) void reduce_kernel(
    const float* __restrict__ bias, float* __restrict__ out)
{
    const int i = blockIdx.x * 256 + threadIdx.x;  // float4 index
    const float4 a = reinterpret_cast<const float4*>(g_part[0])[i];
    const float4 b = reinterpret_cast<const float4*>(g_part[1])[i];
    const float4 c = reinterpret_cast<const float4*>(g_part[2])[i];
    const float4 d = reinterpret_cast<const float4*>(g_part[3])[i];
    const float4 bi = *reinterpret_cast<const float4*>(&bias[(i & 31) << 2]);
    float4 o;
    o.x = a.x + b.x + c.x + d.x + bi.x;
    o.y = a.y + b.y + c.y + d.y + bi.y;
    o.z = a.z + b.z + c.z + d.z + bi.z;
    o.w = a.w + b.w + c.w + d.w + bi.w;
    reinterpret_cast<float4*>(out)[i] = o;
}

extern "C" void kernel_launch(void* const* d_in, const int* in_sizes, int n_in,
                              void* d_out, int out_size)
{
    const float* input = (const float*)d_in[0];  // [4096, 128]
    const float* adj   = (const float*)d_in[1];  // [4096, 4096]
    const float* rel   = (const float*)d_in[2];  // [4096, 128, 128]
    const float* W     = (const float*)d_in[3];  // [4096, 128, 128]
    const float* bias  = (const float*)d_in[4];  // [128]
    float* out = (float*)d_out;                  // [4096, 128]

    cudaFuncSetAttribute(hmma_gemm_kernel,
                         cudaFuncAttributeMaxDynamicSharedMemorySize, SMEM_REQ);

    node_transform_kernel<<<N_NODES, 128>>>(input, rel, W);
    hmma_gemm_kernel<<<dim3(32, SPLITS), 256, SMEM_REQ>>>(adj);
    reduce_kernel<<<(N_NODES * FEA / 4) / 256, 256>>>(bias, out);
}